// round 11
// baseline (speedup 1.0000x reference)
#include <cuda_runtime.h>
#include <cuda_bf16.h>
#include <cstdint>

// BarycentricPooling — stabilized-linear Sinkhorn; R10 numerics, register-dieted
// GEMM for occupancy.
//
// N=20000, S=16, D=128, K=64, B=256, eps=0.1, 21 sweeps (1 log + <=20 linear).
//
// R10 post-mortem: 326us at ~38% issue efficiency, ~5 warps/SMSP resident ->
// latency-bound via register pressure (acc2[16]+P[16] inflate peak regs).
// R11: GEMM in two s-halves (acc2[8]), P[] eliminated (M=P+lb2 streamed to a
// DEDICATED Msh buffer during GEMM, G1/W2 re-read own column), smem no longer
// overlaid (12.9KB/block, not binding). __launch_bounds__(64,12) caps at 85
// regs (natural ~70 after diet -> no spills, unlike R7's 102-cap-vs-130 bust).
// Sweeps, absorbs {4,8,12,16}, early exit, epilogue: verbatim R10 (4.488e-4).

#define SS    16
#define KK    64
#define DD    128
#define BMAX  256
#define MST   65   // Msh row stride (scalar access, conflict-free per phase)
#define L2E_EPS 14.4269504088896340736f   // log2(e)/0.1
#define CTOL  1e-5f

typedef unsigned long long ull;

__device__ float4 g_ctf4[(DD/4)*KK];   // codebook transposed: [d4][k] float4
__device__ float  g_y2[KK];
__device__ float  g_lb2[KK];
__device__ float  g_bk[KK];
__device__ float  g_sums[BMAX*KK];
__device__ float  g_counts[BMAX];

__device__ __forceinline__ float ex2a(float x){ float y; asm("ex2.approx.ftz.f32 %0, %1;" : "=f"(y) : "f"(x)); return y; }
__device__ __forceinline__ float lg2a(float x){ float y; asm("lg2.approx.ftz.f32 %0, %1;" : "=f"(y) : "f"(x)); return y; }
__device__ __forceinline__ float rcpa(float x){ float y; asm("rcp.approx.ftz.f32 %0, %1;" : "=f"(y) : "f"(x)); return y; }
__device__ __forceinline__ void ffma2(ull& d, ull a, ull b){
    asm("fma.rn.f32x2 %0, %1, %2, %0;" : "+l"(d) : "l"(a), "l"(b));
}
__device__ __forceinline__ ull fmul2(ull a, ull b){
    ull r; asm("mul.rn.f32x2 %0, %1, %2;" : "=l"(r) : "l"(a), "l"(b)); return r;
}
__device__ __forceinline__ float unpack_add(ull v){
    float lo = __uint_as_float((unsigned)(v & 0xffffffffull));
    float hi = __uint_as_float((unsigned)(v >> 32));
    return lo + hi;
}
__device__ __forceinline__ ull pk2(float lo, float hi){
    ull r; asm("mov.b64 %0, {%1,%2};" : "=l"(r) : "f"(lo), "f"(hi)); return r;
}

// ---------------------------------------------------------------------------
__global__ void prep_kernel(const float* __restrict__ cb,
                            const float* __restrict__ lp)
{
    __shared__ float sm[2], se[2];
    int tid = threadIdx.x;
    int i = blockIdx.x * blockDim.x + tid;

    if (i < BMAX*KK) g_sums[i] = 0.0f;
    if (i < BMAX)    g_counts[i] = 0.0f;
    if (i < (DD/4)*KK) {
        int d4 = i / KK, k = i % KK;
        const float* r = cb + k*DD + 4*d4;
        g_ctf4[i] = make_float4(r[0], r[1], r[2], r[3]);
    }
    if (blockIdx.x == 0) {
        if (tid < KK*4) {
            int k = tid >> 2, q = tid & 3;
            const float4* r = (const float4*)(cb + k*DD + q*32);
            float s = 0.0f;
            #pragma unroll
            for (int j = 0; j < 8; j++) { float4 v = r[j]; s += v.x*v.x + v.y*v.y + v.z*v.z + v.w*v.w; }
            s += __shfl_xor_sync(0xffffffffu, s, 1);
            s += __shfl_xor_sync(0xffffffffu, s, 2);
            if (q == 0) g_y2[k] = s;
        }
        float v = (tid < KK) ? lp[tid] : -1e30f;
        if (tid < KK) {
            float m = v;
            #pragma unroll
            for (int o = 16; o; o >>= 1) m = fmaxf(m, __shfl_xor_sync(0xffffffffu, m, o));
            if ((tid & 31) == 0) sm[tid >> 5] = m;
        }
        __syncthreads();
        if (tid < KK) {
            float M = fmaxf(sm[0], sm[1]);
            float e = __expf(v - M);
            float s = e;
            #pragma unroll
            for (int o = 16; o; o >>= 1) s += __shfl_xor_sync(0xffffffffu, s, o);
            if ((tid & 31) == 0) se[tid >> 5] = s;
        }
        __syncthreads();
        if (tid < KK) {
            float M = fmaxf(sm[0], sm[1]);
            float lb2 = (v - M) * 1.4426950408889634f - lg2a(se[0] + se[1]);
            g_lb2[tid] = lb2;
            g_bk[tid]  = ex2a(lb2);
        }
    }
}

// ---------------------------------------------------------------------------
__global__ __launch_bounds__(64, 12)
void node_kernel(const float* __restrict__ x,
                 const int*   __restrict__ bidx,
                 int n_nodes)
{
    int node = blockIdx.x;
    if (node >= n_nodes) return;
    const int t  = threadIdx.x;           // 0..63, owns column k=t
    const int fs = t & 15;                // f-direction row
    const int fq = t >> 4;                // f-direction k-quarter

    __shared__ __align__(16) float xsh[SS*DD];      // 8KB, x tile
    __shared__ float Msh[SS*MST];                   // dedicated (no overlay)
    __shared__ __align__(16) float g2s[KK];
    __shared__ float x2sh[SS];
    __shared__ float redm[SS];
    __shared__ __align__(16) float f2[SS];          // F1 then residual u
    __shared__ float red2[2];
    __shared__ int   conv[2];

    // ---------------- stage x ----------------
    {
        const float4* xg4 = (const float4*)(x + (size_t)node * (SS*DD));
        float4* xs4 = (float4*)xsh;
        #pragma unroll
        for (int j = 0; j < 8; j++) xs4[t + 64*j] = xg4[t + 64*j];
    }
    __syncthreads();

    // ---------------- ||x_s||^2 : (s = t&15, d-quarter = t>>4) ----------------
    {
        ull p2 = 0ull;
        #pragma unroll
        for (int i = 0; i < 8; i++) {
            ulonglong2 xp = *(const ulonglong2*)(xsh + fs*DD + fq*32 + i*4);
            ffma2(p2, xp.x, xp.x);
            ffma2(p2, xp.y, xp.y);
        }
        float x2p = unpack_add(p2);
        x2p += __shfl_xor_sync(0xffffffffu, x2p, 16);
        if (t >= 32 && t < 48) redm[fs] = x2p;
        __syncthreads();
        if (t < 16) x2sh[fs] = x2p + redm[fs];
        __syncthreads();
    }

    // ---------------- GEMM in two s-halves; M streamed to Msh ----------------
    const float y2k  = g_y2[t];
    const float lb2k = g_lb2[t];
    float mrun = -1e30f;                  // running max of P over own column

    #pragma unroll 1
    for (int h = 0; h < 2; h++) {
        ull acc2[8];
        #pragma unroll
        for (int si = 0; si < 8; si++) acc2[si] = 0ull;

        #pragma unroll 2
        for (int d4 = 0; d4 < 32; d4++) {
            const ulonglong2 yp = ((const ulonglong2*)g_ctf4)[d4*KK + t];
            #pragma unroll
            for (int si = 0; si < 8; si++) {
                ulonglong2 xp = *(const ulonglong2*)(xsh + (h*8 + si)*DD + d4*4);
                ffma2(acc2[si], xp.x, yp.x);
                ffma2(acc2[si], xp.y, yp.y);
            }
        }
        #pragma unroll
        for (int si = 0; si < 8; si++) {
            int s = h*8 + si;
            float dotv = unpack_add(acc2[si]);
            float Cv = fmaxf(x2sh[s] + y2k - 2.0f*dotv, 0.0f);
            float Pv = -Cv * L2E_EPS;
            mrun = fmaxf(mrun, Pv);
            Msh[s*MST + t] = Pv + lb2k;   // M = P + log2(b); own column, no race
        }
    }

    // ---------------- sweep-1 g: G1 = -lg2 sum 2^P (re-read own column) -------
    float G1;
    {
        const float c = lb2k + mrun;      // M - c = P - mrun
        float e = 0.0f;
        #pragma unroll
        for (int s = 0; s < SS; s++) e += ex2a(Msh[s*MST + t] - c);
        G1 = -(mrun + lg2a(e));
        g2s[t] = G1;
    }
    __syncthreads();

    // ---------------- sweep-1 f (log domain, quarter split) ----------------
    {
        float af[16];
        float mf = -1e30f;
        #pragma unroll
        for (int j = 0; j < 16; j++) {
            int k = fq*16 + j;
            af[j] = g2s[k] + Msh[fs*MST + k];
            mf = fmaxf(mf, af[j]);
        }
        float ef = 0.0f;
        #pragma unroll
        for (int j = 0; j < 16; j++) ef += ex2a(af[j] - mf);
        float mo = __shfl_xor_sync(0xffffffffu, mf, 16);
        float eo = __shfl_xor_sync(0xffffffffu, ef, 16);
        float M2 = fmaxf(mf, mo);
        ef = ef*ex2a(mf - M2) + eo*ex2a(mo - M2);
        if (t >= 32 && t < 48) { redm[fs] = M2; red2[0] = 0.0f; x2sh[fs] = ef; }
        __syncthreads();
        if (t < 16) {
            float M3 = fmaxf(M2, redm[fs]);
            float E  = ef*ex2a(M2 - M3) + x2sh[fs]*ex2a(redm[fs] - M3);
            f2[fs] = -(M3 + lg2a(E));     // F1
        }
        __syncthreads();
    }

    // ---------------- absorb (F1,G1): W2 + Wbq2 packed registers ----------------
    ull W2[8];                            // W[s-pair] for own column t
    {
        const float gl = G1 - lb2k;       // F + G1 + P = F + gl + M
        #pragma unroll
        for (int j = 0; j < 8; j++)
            W2[j] = pk2(ex2a(f2[2*j]   + gl + Msh[(2*j)*MST + t]),
                        ex2a(f2[2*j+1] + gl + Msh[(2*j+1)*MST + t]));
    }
    ull Wbq2[8];                          // Wb[fs][k-pair], quarter fq
    {
        float F1fs = f2[fs];
        #pragma unroll
        for (int j = 0; j < 8; j++) {
            int k = fq*16 + 2*j;
            float wa = ex2a(F1fs + g2s[k]   + Msh[fs*MST + k]);
            float wb = ex2a(F1fs + g2s[k+1] + Msh[fs*MST + k+1]);
            Wbq2[j] = pk2(wa, wb);
        }
    }
    __syncthreads();                      // g2s(G1)/f2(F1) reads done
    if (t < 16) f2[t] = 1.0f;
    if (t == 0) { conv[0] = 1; conv[1] = 1; }
    __syncthreads();

    // ---------------- linear sweeps with early exit ----------------
    float vcur = 1.0f;
    const ull* const u2 = (const ull*)f2;

    #pragma unroll 1
    for (int it = 1; it <= 20; it++) {
        const int par = it & 1;
        // g: V_t = rcp( sum_s u_s W_st )
        ull a0 = 0ull, a1 = 0ull;
        #pragma unroll
        for (int j = 0; j < 8; j += 2) { ffma2(a0, u2[j], W2[j]); ffma2(a1, u2[j+1], W2[j+1]); }
        float cs = unpack_add(a0) + unpack_add(a1);
        vcur = rcpa(fmaxf(cs, 1e-30f));
        if (fabsf(vcur - 1.0f) > CTOL) conv[par] = 0;   // benign race (all write 0)
        g2s[t] = vcur;
        __syncthreads();
        if (t == 0) conv[par ^ 1] = 1;    // prep next iter's flag (slot idle now)
        // f: u_fs = rcp( sum_k V_k Wb_{fs,k} ), quarter split
        const ull* Vp = (const ull*)(g2s + fq*16);
        ull b0 = 0ull, b1 = 0ull;
        #pragma unroll
        for (int j = 0; j < 8; j += 2) { ffma2(b0, Vp[j], Wbq2[j]); ffma2(b1, Vp[j+1], Wbq2[j+1]); }
        float rs = unpack_add(b0) + unpack_add(b1);
        rs += __shfl_xor_sync(0xffffffffu, rs, 16);
        if (t >= 32 && t < 48) redm[fs] = rs;
        __syncthreads();
        if (t < 16) {
            float ucur = rcpa(fmaxf(rs + redm[fs], 1e-30f));
            if (fabsf(ucur - 1.0f) > CTOL) conv[par] = 0;
            f2[fs] = ucur;
        }
        __syncthreads();
        if (conv[par]) break;             // converged: rest are numeric no-ops

        // re-absorb every 4 (underflow ratchet; R4-validated schedule)
        if ((it & 3) == 0 && it != 20) {
            ull vv = pk2(vcur, vcur);
            #pragma unroll
            for (int j = 0; j < 8; j++) W2[j] = fmul2(W2[j], fmul2(u2[j], vv));
            float uf = f2[fs];
            ull  uu = pk2(uf, uf);
            const ull* Vq = (const ull*)(g2s + fq*16);
            #pragma unroll
            for (int j = 0; j < 8; j++) Wbq2[j] = fmul2(Wbq2[j], fmul2(uu, Vq[j]));
            __syncthreads();              // all absorb reads of f2/g2s done
            if (t < 16) f2[t] = 1.0f;
            __syncthreads();
        }
    }

    // ---------------- histogram: h_k = b_k * V_k * sum_s u_s W_sk ----------------
    {
        ull a0 = 0ull, a1 = 0ull;
        #pragma unroll
        for (int j = 0; j < 8; j += 2) { ffma2(a0, u2[j], W2[j]); ffma2(a1, u2[j+1], W2[j+1]); }
        float cs2 = unpack_add(a0) + unpack_add(a1);
        float hk = g_bk[t] * vcur * cs2;

        float ws = hk;
        #pragma unroll
        for (int o = 16; o; o >>= 1) ws += __shfl_xor_sync(0xffffffffu, ws, o);
        if ((t & 31) == 0) red2[t >> 5] = ws;
        __syncthreads();
        float inv = rcpa(fmaxf(red2[0] + red2[1], 1e-30f));

        int b = bidx[node];
        atomicAdd(&g_sums[b*KK + t], hk * inv);
        if (t == 0) atomicAdd(&g_counts[b], 1.0f);
    }
}

// ---------------------------------------------------------------------------
__global__ void final_kernel(float* __restrict__ out, int B)
{
    int b = blockIdx.x, k = threadIdx.x;
    if (b >= B) return;
    float c = g_counts[b];
    float v = (c > 0.0f) ? (g_sums[b*KK + k] / c) : g_bk[k];
    out[b*KK + k] = v;
}

// ---------------------------------------------------------------------------
extern "C" void kernel_launch(void* const* d_in, const int* in_sizes, int n_in,
                              void* d_out, int out_size)
{
    const float* x    = (const float*)d_in[0];   // [N,16,128] f32
    const int*   bi   = (const int*)  d_in[1];   // [N] int32
    const float* cb   = (const float*)d_in[2];   // [64,128] f32
    const float* lp   = (const float*)d_in[3];   // [64] f32
    int N = in_sizes[1];
    int B = out_size / KK;
    if (B > BMAX) B = BMAX;

    prep_kernel<<<64, 256>>>(cb, lp);
    node_kernel<<<N, 64>>>(x, bi, N);
    final_kernel<<<B, KK>>>((float*)d_out, B);
}

// round 15
// speedup vs baseline: 2.0358x; 2.0358x over previous
#include <cuda_runtime.h>
#include <cuda_bf16.h>
#include <cstdint>

// BarycentricPooling — mma.sync (HMMA bf16, 4-pass exact split) GEMM
// + R10-proven stabilized-linear Sinkhorn groups.
//
// N=20000, S=16, D=128, K=64, B=256, eps=0.1, 21 sweeps (1 log + <=20 linear).
//
// R12 lesson: harness compiles at compute_103 (no 'a') -> tcgen05 unavailable;
// mma.sync m16n8k16 bf16 (sm_80 base PTX) is the legal tensor-core route.
// R13->R14 fix: the C->M epilogue used float2 stores at Msh+g8*MST+n0 with
// MST=65 (odd) -> 8B-misaligned for odd g8 (UB). Now scalar stores.
//
// Block = 256 threads = 4 nodes (group g = tid>>6, 2 warps each).
//   bS (smem): codebook hi/lo, [v][n][136] halves (pad -> conflict-free frags).
//   aS (smem): per node x hi/lo, [v][16][136] halves.
//   GEMM: per warp 4 n-tiles x 8 k-steps x 4 passes = 128 HMMA, f32 accum.
//   M = -C*log2e/eps + log2(b) overlays the node's aS region (dead post-GEMM).
//   Sinkhorn: R10-verbatim group code under named barriers 1..4
//   (absorbs at 4/8/12/16 = underflow ratchet; early exit; 4.488e-4 validated).

#define SS    16
#define KK    64
#define DD    128
#define BMAX  256
#define NPB   4
#define NTHR  256
#define MST   65
#define AST   136                         // A/B row stride in halves (pad 8)
#define L2E_EPS 14.4269504088896340736f
#define CTOL  1e-5f

typedef unsigned long long ull;

__device__ __align__(16) __nv_bfloat16 g_Bt[2*KK*AST]; // [v][n][136] halves
__device__ float g_y2[KK], g_lb2[KK], g_bk[KK];
__device__ float g_sums[BMAX*KK], g_counts[BMAX];

__device__ __forceinline__ float ex2a(float x){ float y; asm("ex2.approx.ftz.f32 %0, %1;" : "=f"(y) : "f"(x)); return y; }
__device__ __forceinline__ float lg2a(float x){ float y; asm("lg2.approx.ftz.f32 %0, %1;" : "=f"(y) : "f"(x)); return y; }
__device__ __forceinline__ float rcpa(float x){ float y; asm("rcp.approx.ftz.f32 %0, %1;" : "=f"(y) : "f"(x)); return y; }
__device__ __forceinline__ void ffma2(ull& d, ull a, ull b){
    asm("fma.rn.f32x2 %0, %1, %2, %0;" : "+l"(d) : "l"(a), "l"(b));
}
__device__ __forceinline__ ull fmul2(ull a, ull b){
    ull r; asm("mul.rn.f32x2 %0, %1, %2;" : "=l"(r) : "l"(a), "l"(b)); return r;
}
__device__ __forceinline__ float unpack_add(ull v){
    float lo = __uint_as_float((unsigned)(v & 0xffffffffull));
    float hi = __uint_as_float((unsigned)(v >> 32));
    return lo + hi;
}
__device__ __forceinline__ ull pk2(float lo, float hi){
    ull r; asm("mov.b64 %0, {%1,%2};" : "=l"(r) : "f"(lo), "f"(hi)); return r;
}
__device__ __forceinline__ uint32_t bfpack(float a, float b){
    __nv_bfloat162 t = __floats2bfloat162_rn(a, b);   // low half = a
    return *(uint32_t*)&t;
}
#define GBAR(id) asm volatile("bar.sync %0, %1;" :: "r"(id), "r"(64) : "memory")

__device__ __forceinline__ void mma16816(float* c, uint32_t a0, uint32_t a1,
                                         uint32_t a2, uint32_t a3,
                                         uint32_t b0, uint32_t b1){
    asm volatile(
        "mma.sync.aligned.m16n8k16.row.col.f32.bf16.bf16.f32 "
        "{%0,%1,%2,%3}, {%4,%5,%6,%7}, {%8,%9}, {%0,%1,%2,%3};"
        : "+f"(c[0]), "+f"(c[1]), "+f"(c[2]), "+f"(c[3])
        : "r"(a0), "r"(a1), "r"(a2), "r"(a3), "r"(b0), "r"(b1));
}

// ---------------------------------------------------------------------------
__global__ void prep_kernel(const float* __restrict__ cb,
                            const float* __restrict__ lp)
{
    __shared__ float sm[2], se[2];
    int tid = threadIdx.x;
    int i = blockIdx.x * blockDim.x + tid;      // 0..16383

    if (i < BMAX*KK) g_sums[i] = 0.0f;
    if (i < BMAX)    g_counts[i] = 0.0f;

    if (i < KK*DD) {                      // split codebook hi/lo into g_Bt
        int n = i >> 7, d = i & 127;
        float v = cb[n*DD + d];
        __nv_bfloat16 h = __float2bfloat16(v);
        float l = v - __bfloat162float(h);
        g_Bt[n*AST + d]            = h;
        g_Bt[KK*AST + n*AST + d]   = __float2bfloat16(l);
    }
    if (i < 2*KK) {                       // zero the 8-half pad of each row
        int row = i;                      // covers both hi and lo blocks
        #pragma unroll
        for (int p = 0; p < 8; p++) g_Bt[row*AST + DD + p] = __float2bfloat16(0.0f);
    }
    if (blockIdx.x == 0) {
        if (tid < KK*4) {
            int k = tid >> 2, q = tid & 3;
            const float4* r = (const float4*)(cb + k*DD + q*32);
            float s = 0.0f;
            #pragma unroll
            for (int j = 0; j < 8; j++) { float4 v = r[j]; s += v.x*v.x + v.y*v.y + v.z*v.z + v.w*v.w; }
            s += __shfl_xor_sync(0xffffffffu, s, 1);
            s += __shfl_xor_sync(0xffffffffu, s, 2);
            if (q == 0) g_y2[k] = s;
        }
        float v = (tid < KK) ? lp[tid] : -1e30f;
        if (tid < KK) {
            float m = v;
            #pragma unroll
            for (int o = 16; o; o >>= 1) m = fmaxf(m, __shfl_xor_sync(0xffffffffu, m, o));
            if ((tid & 31) == 0) sm[tid >> 5] = m;
        }
        __syncthreads();
        if (tid < KK) {
            float M = fmaxf(sm[0], sm[1]);
            float e = __expf(v - M);
            float s = e;
            #pragma unroll
            for (int o = 16; o; o >>= 1) s += __shfl_xor_sync(0xffffffffu, s, o);
            if ((tid & 31) == 0) se[tid >> 5] = s;
        }
        __syncthreads();
        if (tid < KK) {
            float M = fmaxf(sm[0], sm[1]);
            float lb2 = (v - M) * 1.4426950408889634f - lg2a(se[0] + se[1]);
            g_lb2[tid] = lb2;
            g_bk[tid]  = ex2a(lb2);
        }
    }
}

// ---------------------------------------------------------------------------
// dyn smem: bS 2*64*136 halves (34816B) | aS 4 nodes x 2*16*136 halves (8704B each)
#define DYN_BYTES (34816 + NPB*8704)

__global__ void node_kernel(const float* __restrict__ x,
                            const int*   __restrict__ bidx,
                            int n_nodes)
{
    extern __shared__ __align__(16) char dyn[];
    __nv_bfloat16* const bS = (__nv_bfloat16*)dyn;            // [v][n][AST]
    __nv_bfloat16* const aS = bS + 2*KK*AST;                  // per node [v][16][AST]

    __shared__ float x2a[NPB][SS];
    __shared__ float y2s[KK], lb2s[KK], bks[KK];
    __shared__ __align__(16) float g2s[NPB][KK];
    __shared__ __align__(16) float f2s[NPB][SS];
    __shared__ float redm[NPB][SS], efm[NPB][SS];
    __shared__ float red2[NPB][2];
    __shared__ int   conv[NPB][2];

    const int tid = threadIdx.x;
    const int g   = tid >> 6;             // node group 0..3
    const int lt  = tid & 63;
    const int lane = tid & 31;
    const int w01 = lt >> 5;              // warp within group: n-half
    const int g8  = lane >> 2;            // mma groupID
    const int tg  = lane & 3;             // mma thread-in-group
    const int node = blockIdx.x * NPB + g;
    const bool valid = node < n_nodes;
    const int bar = g + 1;

    // ---------------- stage B (whole block) + y2/lb2/bk ----------------
    {
        const uint4* bg = (const uint4*)g_Bt;
        uint4* bs4 = (uint4*)bS;
        for (int i = tid; i < 2176; i += NTHR) bs4[i] = bg[i];
        if (tid < KK) { y2s[tid] = g_y2[tid]; lb2s[tid] = g_lb2[tid]; bks[tid] = g_bk[tid]; }
    }

    // ---------------- stage A: convert x -> hi/lo bf16 + x2 ----------------
    {
        int r = lt >> 2, q = lt & 3;      // row 0..15, k-quarter 0..3
        const float4* xr = (const float4*)(x + (size_t)(valid ? node : 0)*(SS*DD) + r*DD + q*32);
        __nv_bfloat16* aH = aS + g*2*SS*AST + r*AST + q*32;
        __nv_bfloat16* aL = aH + SS*AST;
        float x2 = 0.0f;
        #pragma unroll
        for (int i = 0; i < 8; i++) {
            float4 v = valid ? xr[i] : make_float4(0.f,0.f,0.f,0.f);
            __nv_bfloat16 hx = __float2bfloat16(v.x), hy = __float2bfloat16(v.y);
            __nv_bfloat16 hz = __float2bfloat16(v.z), hw = __float2bfloat16(v.w);
            uint32_t h01, h23;
            { __nv_bfloat162 p(hx, hy); h01 = *(uint32_t*)&p; }
            { __nv_bfloat162 p(hz, hw); h23 = *(uint32_t*)&p; }
            uint32_t l01 = bfpack(v.x - __bfloat162float(hx), v.y - __bfloat162float(hy));
            uint32_t l23 = bfpack(v.z - __bfloat162float(hz), v.w - __bfloat162float(hw));
            *(uint2*)(aH + i*4) = make_uint2(h01, h23);
            *(uint2*)(aL + i*4) = make_uint2(l01, l23);
            x2 += v.x*v.x + v.y*v.y + v.z*v.z + v.w*v.w;
        }
        x2 += __shfl_xor_sync(0xffffffffu, x2, 1);
        x2 += __shfl_xor_sync(0xffffffffu, x2, 2);
        if (q == 0) x2a[g][r] = x2;
    }
    __syncthreads();

    // ---------------- GEMM: 4 passes x 8 k-steps x 4 n-tiles ----------------
    float c[4][4];
    #pragma unroll
    for (int nt = 0; nt < 4; nt++)
        #pragma unroll
        for (int j = 0; j < 4; j++) c[nt][j] = 0.0f;

    {
        const __nv_bfloat16* aBase = aS + g*2*SS*AST;
        const int n0base = w01*32;
        #pragma unroll 1
        for (int p = 0; p < 4; p++) {
            const int Av = p >> 1, Bv = p & 1;
            const __nv_bfloat16* aV = aBase + Av*SS*AST;
            const __nv_bfloat16* bV = bS + Bv*KK*AST;
            #pragma unroll
            for (int ks = 0; ks < 8; ks++) {
                const int k0 = ks*16;
                uint32_t a0 = *(const uint32_t*)(aV + g8*AST     + k0 + 2*tg);
                uint32_t a1 = *(const uint32_t*)(aV + (g8+8)*AST + k0 + 2*tg);
                uint32_t a2 = *(const uint32_t*)(aV + g8*AST     + k0 + 2*tg + 8);
                uint32_t a3 = *(const uint32_t*)(aV + (g8+8)*AST + k0 + 2*tg + 8);
                #pragma unroll
                for (int nt = 0; nt < 4; nt++) {
                    const __nv_bfloat16* bp = bV + (n0base + nt*8 + g8)*AST + k0 + 2*tg;
                    uint32_t b0 = *(const uint32_t*)bp;
                    uint32_t b1 = *(const uint32_t*)(bp + 8);
                    mma16816(c[nt], a0, a1, a2, a3, b0, b1);
                }
            }
        }
    }
    GBAR(bar);                            // both warps done reading aS[g]

    // ---------------- C -> M = -C*log2e/eps + log2(b), overlay aS[g] ----------
    // Scalar stores only: MST=65 is odd, float2 would be 8B-misaligned (R13 bug).
    float* const Msh = (float*)(aS + g*2*SS*AST);
    {
        float x2r0 = x2a[g][g8], x2r1 = x2a[g][g8+8];
        #pragma unroll
        for (int nt = 0; nt < 4; nt++) {
            int n0 = w01*32 + nt*8 + 2*tg;
            float y20 = y2s[n0],   y21 = y2s[n0+1];
            float lb0 = lb2s[n0],  lb1 = lb2s[n0+1];
            Msh[g8*MST     + n0    ] = -fmaxf(x2r0 + y20 - 2.0f*c[nt][0], 0.0f)*L2E_EPS + lb0;
            Msh[g8*MST     + n0 + 1] = -fmaxf(x2r0 + y21 - 2.0f*c[nt][1], 0.0f)*L2E_EPS + lb1;
            Msh[(g8+8)*MST + n0    ] = -fmaxf(x2r1 + y20 - 2.0f*c[nt][2], 0.0f)*L2E_EPS + lb0;
            Msh[(g8+8)*MST + n0 + 1] = -fmaxf(x2r1 + y21 - 2.0f*c[nt][3], 0.0f)*L2E_EPS + lb1;
        }
    }
    GBAR(bar);

    // ---------------- Sinkhorn (R10 numerics, group-scoped) ----------------
    if (valid) {
        const int fs = lt & 15, fq = lt >> 4;
        const float lb2k = lb2s[lt];

        // sweep-1 g: own column (k = lt)
        float Mc[SS];
        #pragma unroll
        for (int s = 0; s < SS; s++) Mc[s] = Msh[s*MST + lt];
        float mx = Mc[0];
        #pragma unroll
        for (int s = 1; s < SS; s++) mx = fmaxf(mx, Mc[s]);
        float e = 0.0f;
        #pragma unroll
        for (int s = 0; s < SS; s++) e += ex2a(Mc[s] - mx);
        float G1 = -((mx - lb2k) + lg2a(e));
        g2s[g][lt] = G1;
        GBAR(bar);

        // sweep-1 f (quarter split)
        {
            float af[16], mf = -1e30f;
            #pragma unroll
            for (int j = 0; j < 16; j++) {
                int k = fq*16 + j;
                af[j] = g2s[g][k] + Msh[fs*MST + k];
                mf = fmaxf(mf, af[j]);
            }
            float ef = 0.0f;
            #pragma unroll
            for (int j = 0; j < 16; j++) ef += ex2a(af[j] - mf);
            float mo = __shfl_xor_sync(0xffffffffu, mf, 16);
            float eo = __shfl_xor_sync(0xffffffffu, ef, 16);
            float M2 = fmaxf(mf, mo);
            ef = ef*ex2a(mf - M2) + eo*ex2a(mo - M2);
            if (lt >= 32 && lt < 48) { redm[g][fs] = M2; efm[g][fs] = ef; }
            GBAR(bar);
            if (lt < 16) {
                float M3 = fmaxf(M2, redm[g][fs]);
                float E  = ef*ex2a(M2 - M3) + efm[g][fs]*ex2a(redm[g][fs] - M3);
                f2s[g][fs] = -(M3 + lg2a(E));    // F1
            }
            GBAR(bar);
        }

        // absorb (F1,G1)
        ull W2[8];
        {
            const float gl = G1 - lb2k;
            #pragma unroll
            for (int j = 0; j < 8; j++)
                W2[j] = pk2(ex2a(f2s[g][2*j] + gl + Mc[2*j]),
                            ex2a(f2s[g][2*j+1] + gl + Mc[2*j+1]));
        }
        ull Wbq2[8];
        {
            float F1fs = f2s[g][fs];
            #pragma unroll
            for (int j = 0; j < 8; j++) {
                int k = fq*16 + 2*j;
                float wa = ex2a(F1fs + g2s[g][k]   + Msh[fs*MST + k]);
                float wb = ex2a(F1fs + g2s[g][k+1] + Msh[fs*MST + k+1]);
                Wbq2[j] = pk2(wa, wb);
            }
        }
        GBAR(bar);
        if (lt < 16) f2s[g][lt] = 1.0f;
        if (lt == 0) { conv[g][0] = 1; conv[g][1] = 1; }
        GBAR(bar);

        // linear sweeps with early exit + absorbs at 4/8/12/16
        float vcur = 1.0f;
        const ull* const u2 = (const ull*)f2s[g];

        #pragma unroll 1
        for (int it = 1; it <= 20; it++) {
            const int par = it & 1;
            ull a0 = 0ull, a1 = 0ull;
            #pragma unroll
            for (int j = 0; j < 8; j += 2) { ffma2(a0, u2[j], W2[j]); ffma2(a1, u2[j+1], W2[j+1]); }
            float cs = unpack_add(a0) + unpack_add(a1);
            vcur = rcpa(fmaxf(cs, 1e-30f));
            if (fabsf(vcur - 1.0f) > CTOL) conv[g][par] = 0;
            g2s[g][lt] = vcur;
            GBAR(bar);
            if (lt == 0) conv[g][par ^ 1] = 1;
            const ull* Vp = (const ull*)(g2s[g] + fq*16);
            ull b0 = 0ull, b1 = 0ull;
            #pragma unroll
            for (int j = 0; j < 8; j += 2) { ffma2(b0, Vp[j], Wbq2[j]); ffma2(b1, Vp[j+1], Wbq2[j+1]); }
            float rs = unpack_add(b0) + unpack_add(b1);
            rs += __shfl_xor_sync(0xffffffffu, rs, 16);
            if (lt >= 32 && lt < 48) redm[g][fs] = rs;
            GBAR(bar);
            if (lt < 16) {
                float ucur = rcpa(fmaxf(rs + redm[g][fs], 1e-30f));
                if (fabsf(ucur - 1.0f) > CTOL) conv[g][par] = 0;
                f2s[g][fs] = ucur;
            }
            GBAR(bar);
            if (conv[g][par]) break;

            if ((it & 3) == 0 && it != 20) {
                ull vv = pk2(vcur, vcur);
                #pragma unroll
                for (int j = 0; j < 8; j++) W2[j] = fmul2(W2[j], fmul2(u2[j], vv));
                float uf = f2s[g][fs];
                ull  uu = pk2(uf, uf);
                const ull* Vq = (const ull*)(g2s[g] + fq*16);
                #pragma unroll
                for (int j = 0; j < 8; j++) Wbq2[j] = fmul2(Wbq2[j], fmul2(uu, Vq[j]));
                GBAR(bar);
                if (lt < 16) f2s[g][lt] = 1.0f;
                GBAR(bar);
            }
        }

        // histogram
        {
            ull a0 = 0ull, a1 = 0ull;
            #pragma unroll
            for (int j = 0; j < 8; j += 2) { ffma2(a0, u2[j], W2[j]); ffma2(a1, u2[j+1], W2[j+1]); }
            float cs2 = unpack_add(a0) + unpack_add(a1);
            float hk = bks[lt] * vcur * cs2;

            float ws = hk;
            #pragma unroll
            for (int o = 16; o; o >>= 1) ws += __shfl_xor_sync(0xffffffffu, ws, o);
            if ((lt & 31) == 0) red2[g][lt >> 5] = ws;
            GBAR(bar);
            float inv = rcpa(fmaxf(red2[g][0] + red2[g][1], 1e-30f));

            int b = bidx[node];
            atomicAdd(&g_sums[b*KK + lt], hk * inv);
            if (lt == 0) atomicAdd(&g_counts[b], 1.0f);
        }
    }
}

// ---------------------------------------------------------------------------
__global__ void final_kernel(float* __restrict__ out, int B)
{
    int b = blockIdx.x, k = threadIdx.x;
    if (b >= B) return;
    float c = g_counts[b];
    float v = (c > 0.0f) ? (g_sums[b*KK + k] / c) : g_bk[k];
    out[b*KK + k] = v;
}

// ---------------------------------------------------------------------------
extern "C" void kernel_launch(void* const* d_in, const int* in_sizes, int n_in,
                              void* d_out, int out_size)
{
    const float* x    = (const float*)d_in[0];   // [N,16,128] f32
    const int*   bi   = (const int*)  d_in[1];   // [N] int32
    const float* cb   = (const float*)d_in[2];   // [64,128] f32
    const float* lp   = (const float*)d_in[3];   // [64] f32
    int N = in_sizes[1];
    int B = out_size / KK;
    if (B > BMAX) B = BMAX;

    cudaFuncSetAttribute(node_kernel, cudaFuncAttributeMaxDynamicSharedMemorySize, DYN_BYTES);

    prep_kernel<<<64, 256>>>(cb, lp);
    node_kernel<<<(N + NPB - 1)/NPB, NTHR, DYN_BYTES>>>(x, bi, N);
    final_kernel<<<B, KK>>>((float*)d_out, B);
}

// round 16
// speedup vs baseline: 2.4603x; 1.2085x over previous
#include <cuda_runtime.h>
#include <cuda_bf16.h>
#include <cstdint>

// BarycentricPooling — warp-autonomous nodes: HMMA bf16-split GEMM + fully
// warp-synchronous stabilized-linear Sinkhorn (zero bar.sync after staging).
//
// N=20000, S=16, D=128, K=64, B=256, eps=0.1, 21 sweeps (1 log + <=20 linear).
//
// Block = 256 threads = 8 warps = 8 nodes. Per warp:
//   GEMM: full 16x64 C via m16n8k16 bf16 (4-pass exact hi/lo split, PTX-
//   verified fragment maps from R15). k-interleaved smem layout (per 16-half
//   group order [2t,2t+1,2t+8,2t+9,...], row stride 288B == 8 mod 32 words)
//   -> every A/B fragment is ONE conflict-free LDS.64.
//   Sinkhorn: lane owns cols {l, l+32} (g) and row l&15 / k-half l>>4 (f);
//   V/u exchange via node-private smem + __syncwarp; shfl_xor(16) merge;
//   early exit via __all_sync; absorbs at {4,8,12,16} (R10 semantics,
//   4.488e-4 validated).
// Msh (16x66 f32) + V/u overlay the node's dead A smem planes.

#define SS    16
#define KK    64
#define DD    128
#define BMAX  256
#define NPB   8
#define NTHR  256
#define AST   144                 // halves per row (288B; 72 words == 8 mod 32)
#define APL   (SS*AST)            // halves per A plane (2304)
#define MST   66
#define L2E_EPS 14.4269504088896340736f
#define CTOL  1e-5f
#define FULLM 0xffffffffu

typedef unsigned long long ull;

__device__ __align__(16) __nv_bfloat16 g_Bt[2*KK*AST]; // [v][n][AST] k-interleaved
__device__ float g_y2[KK], g_lb2[KK], g_bk[KK];
__device__ float g_sums[BMAX*KK], g_counts[BMAX];

__device__ __forceinline__ float ex2a(float x){ float y; asm("ex2.approx.ftz.f32 %0, %1;" : "=f"(y) : "f"(x)); return y; }
__device__ __forceinline__ float lg2a(float x){ float y; asm("lg2.approx.ftz.f32 %0, %1;" : "=f"(y) : "f"(x)); return y; }
__device__ __forceinline__ float rcpa(float x){ float y; asm("rcp.approx.ftz.f32 %0, %1;" : "=f"(y) : "f"(x)); return y; }
__device__ __forceinline__ void ffma2(ull& d, ull a, ull b){
    asm("fma.rn.f32x2 %0, %1, %2, %0;" : "+l"(d) : "l"(a), "l"(b));
}
__device__ __forceinline__ ull fmul2(ull a, ull b){
    ull r; asm("mul.rn.f32x2 %0, %1, %2;" : "=l"(r) : "l"(a), "l"(b)); return r;
}
__device__ __forceinline__ float unpack_add(ull v){
    float lo = __uint_as_float((unsigned)(v & 0xffffffffull));
    float hi = __uint_as_float((unsigned)(v >> 32));
    return lo + hi;
}
__device__ __forceinline__ ull pk2(float lo, float hi){
    ull r; asm("mov.b64 %0, {%1,%2};" : "=l"(r) : "f"(lo), "f"(hi)); return r;
}
__device__ __forceinline__ uint32_t bfpack(float a, float b){
    __nv_bfloat162 t = __floats2bfloat162_rn(a, b);   // low half = a
    return *(uint32_t*)&t;
}
__device__ __forceinline__ void mma16816(float* c, uint32_t a0, uint32_t a1,
                                         uint32_t a2, uint32_t a3,
                                         uint32_t b0, uint32_t b1){
    asm volatile(
        "mma.sync.aligned.m16n8k16.row.col.f32.bf16.bf16.f32 "
        "{%0,%1,%2,%3}, {%4,%5,%6,%7}, {%8,%9}, {%0,%1,%2,%3};"
        : "+f"(c[0]), "+f"(c[1]), "+f"(c[2]), "+f"(c[3])
        : "r"(a0), "r"(a1), "r"(a2), "r"(a3), "r"(b0), "r"(b1));
}
// perm within a 16-half k-group: k -> [2t,2t+1,2t+8,2t+9] contiguous per tg
__device__ __host__ __forceinline__ int kperm(int j){
    return 4*((j&7)>>1) + (j&1) + 2*(j>>3);
}

// ---------------------------------------------------------------------------
__global__ void prep_kernel(const float* __restrict__ cb,
                            const float* __restrict__ lp)
{
    __shared__ float sm[2], se[2];
    int tid = threadIdx.x;
    int i = blockIdx.x * blockDim.x + tid;      // 0..16383

    if (i < BMAX*KK) g_sums[i] = 0.0f;
    if (i < BMAX)    g_counts[i] = 0.0f;

    if (i < KK*DD) {                      // split codebook hi/lo, k-interleaved
        int n = i >> 7, d = i & 127;
        float v = cb[n*DD + d];
        __nv_bfloat16 h = __float2bfloat16(v);
        float l = v - __bfloat162float(h);
        int pos = n*AST + (d & ~15) + kperm(d & 15);
        g_Bt[pos]          = h;
        g_Bt[KK*AST + pos] = __float2bfloat16(l);
    }
    if (blockIdx.x == 0) {
        if (tid < KK*4) {
            int k = tid >> 2, q = tid & 3;
            const float4* r = (const float4*)(cb + k*DD + q*32);
            float s = 0.0f;
            #pragma unroll
            for (int j = 0; j < 8; j++) { float4 v = r[j]; s += v.x*v.x + v.y*v.y + v.z*v.z + v.w*v.w; }
            s += __shfl_xor_sync(FULLM, s, 1);
            s += __shfl_xor_sync(FULLM, s, 2);
            if (q == 0) g_y2[k] = s;
        }
        float v = (tid < KK) ? lp[tid] : -1e30f;
        if (tid < KK) {
            float m = v;
            #pragma unroll
            for (int o = 16; o; o >>= 1) m = fmaxf(m, __shfl_xor_sync(FULLM, m, o));
            if ((tid & 31) == 0) sm[tid >> 5] = m;
        }
        __syncthreads();
        if (tid < KK) {
            float M = fmaxf(sm[0], sm[1]);
            float e = __expf(v - M);
            float s = e;
            #pragma unroll
            for (int o = 16; o; o >>= 1) s += __shfl_xor_sync(FULLM, s, o);
            if ((tid & 31) == 0) se[tid >> 5] = s;
        }
        __syncthreads();
        if (tid < KK) {
            float M = fmaxf(sm[0], sm[1]);
            float lb2 = (v - M) * 1.4426950408889634f - lg2a(se[0] + se[1]);
            g_lb2[tid] = lb2;
            g_bk[tid]  = ex2a(lb2);
        }
    }
}

// ---------------------------------------------------------------------------
// dyn smem: bS 2*64*AST halves (36864B) + 8 nodes x 2 A planes (9216B each)
#define DYN_BYTES (2*KK*AST*2 + NPB*2*APL*2)   // 110592

__global__ __launch_bounds__(NTHR, 2)
void node_kernel(const float* __restrict__ x,
                 const int*   __restrict__ bidx,
                 int n_nodes)
{
    extern __shared__ __align__(16) char dyn[];
    __nv_bfloat16* const bS = (__nv_bfloat16*)dyn;       // [v][64][AST]
    __nv_bfloat16* const aS = bS + 2*KK*AST;             // [NPB][v][16][AST]

    const int tid = threadIdx.x;
    const int w   = tid >> 5;             // warp = node group 0..7
    const int l   = tid & 31;
    const int g8  = l >> 2;               // mma groupID
    const int tg  = l & 3;                // mma thread-in-group
    const int node = blockIdx.x * NPB + w;
    const bool valid = node < n_nodes;

    // ---------------- stage B (whole block) ----------------
    {
        const uint4* bg = (const uint4*)g_Bt;
        uint4* bs4 = (uint4*)bS;
        for (int i = tid; i < 2304; i += NTHR) bs4[i] = bg[i];
    }

    // ---------------- stage A (per warp): hi/lo bf16, interleaved + x2 ------
    float x2 = 0.0f;
    if (valid) {
        int r = l >> 1, q2 = l & 1;       // row, k-half of row
        const float4* xr = (const float4*)(x + (size_t)node*(SS*DD) + r*DD + q2*64);
        uint32_t* aH = (uint32_t*)(aS + w*2*APL + r*AST);
        uint32_t* aL = aH + APL/2;
        #pragma unroll
        for (int i = 0; i < 16; i++) {
            int k = q2*64 + 4*i;
            int grp = k >> 4, j = k & 15;              // j in {0,4,8,12}
            int p1 = grp*8 + 2*((j&7)>>1) + (j>>3);    // u32 slot of (k,k+1)
            float4 v = xr[i];
            __nv_bfloat16 hx = __float2bfloat16(v.x), hy = __float2bfloat16(v.y);
            __nv_bfloat16 hz = __float2bfloat16(v.z), hw = __float2bfloat16(v.w);
            uint32_t h01, h23;
            { __nv_bfloat162 p(hx, hy); h01 = *(uint32_t*)&p; }
            { __nv_bfloat162 p(hz, hw); h23 = *(uint32_t*)&p; }
            aH[p1]     = h01;
            aH[p1 + 2] = h23;                          // (k+2,k+3) slot
            aL[p1]     = bfpack(v.x - __bfloat162float(hx), v.y - __bfloat162float(hy));
            aL[p1 + 2] = bfpack(v.z - __bfloat162float(hz), v.w - __bfloat162float(hw));
            x2 += v.x*v.x + v.y*v.y + v.z*v.z + v.w*v.w;
        }
        x2 += __shfl_xor_sync(FULLM, x2, 1);           // full row-r sum, both lanes
    }
    __syncthreads();                       // bS + aS visible (only block barrier)

    if (!valid) return;

    // ---------------- GEMM: per warp full 16x64, 4-pass split ----------------
    float c[8][4];
    #pragma unroll
    for (int nt = 0; nt < 8; nt++)
        #pragma unroll
        for (int j = 0; j < 4; j++) c[nt][j] = 0.0f;
    {
        const __nv_bfloat16* aHi = aS + w*2*APL;
        const __nv_bfloat16* aLo = aHi + APL;
        const __nv_bfloat16* bHi = bS;
        const __nv_bfloat16* bLo = bS + KK*AST;
        #pragma unroll 2
        for (int ks = 0; ks < 8; ks++) {
            const int o = ks*16 + 4*tg;
            uint2 Ah0 = *(const uint2*)(aHi + g8*AST + o);       // (a0,a2)
            uint2 Ah1 = *(const uint2*)(aHi + (g8+8)*AST + o);   // (a1,a3)
            uint2 Al0 = *(const uint2*)(aLo + g8*AST + o);
            uint2 Al1 = *(const uint2*)(aLo + (g8+8)*AST + o);
            #pragma unroll
            for (int nt = 0; nt < 8; nt++) {
                uint2 Bh = *(const uint2*)(bHi + (nt*8+g8)*AST + o);
                uint2 Bl = *(const uint2*)(bLo + (nt*8+g8)*AST + o);
                mma16816(c[nt], Ah0.x, Ah1.x, Ah0.y, Ah1.y, Bh.x, Bh.y);  // hh
                mma16816(c[nt], Ah0.x, Ah1.x, Ah0.y, Ah1.y, Bl.x, Bl.y);  // hl
                mma16816(c[nt], Al0.x, Al1.x, Al0.y, Al1.y, Bh.x, Bh.y);  // lh
                mma16816(c[nt], Al0.x, Al1.x, Al0.y, Al1.y, Bl.x, Bl.y);  // ll
            }
        }
    }
    __syncwarp();                          // all frag reads done before overlay

    // ---------------- C -> M = -C*log2e/eps + log2(b), overlay A planes ------
    float* const Msh  = (float*)(aS + w*2*APL);           // 16 x MST (4224B)
    float* const g2s  = (float*)(aS + w*2*APL + APL);     // [64] (lo plane, dead)
    float* const f2s  = g2s + KK;                         // [16]
    {
        float x2r0 = __shfl_sync(FULLM, x2, 2*g8);
        float x2r1 = __shfl_sync(FULLM, x2, 2*g8 + 16);
        #pragma unroll
        for (int nt = 0; nt < 8; nt++) {
            int n0 = nt*8 + 2*tg;
            float y20 = g_y2[n0],  y21 = g_y2[n0+1];
            float lb0 = g_lb2[n0], lb1 = g_lb2[n0+1];
            float m00 = -fmaxf(x2r0 + y20 - 2.0f*c[nt][0], 0.0f)*L2E_EPS + lb0;
            float m01 = -fmaxf(x2r0 + y21 - 2.0f*c[nt][1], 0.0f)*L2E_EPS + lb1;
            float m10 = -fmaxf(x2r1 + y20 - 2.0f*c[nt][2], 0.0f)*L2E_EPS + lb0;
            float m11 = -fmaxf(x2r1 + y21 - 2.0f*c[nt][3], 0.0f)*L2E_EPS + lb1;
            *(float2*)(Msh + g8*MST     + n0) = make_float2(m00, m01);   // n0 even: 8B ok
            *(float2*)(Msh + (g8+8)*MST + n0) = make_float2(m10, m11);
        }
    }
    __syncwarp();

    // ---------------- sweep-1 g: G1 per column (cols l, l+32) ----------------
    const float lbA = g_lb2[l], lbB = g_lb2[l+32];
    float G1a, G1b;
    {
        float Ma[SS], Mb[SS];
        #pragma unroll
        for (int s = 0; s < SS; s++) { Ma[s] = Msh[s*MST + l]; Mb[s] = Msh[s*MST + l + 32]; }
        float mxa = Ma[0], mxb = Mb[0];
        #pragma unroll
        for (int s = 1; s < SS; s++) { mxa = fmaxf(mxa, Ma[s]); mxb = fmaxf(mxb, Mb[s]); }
        float ea = 0.0f, eb = 0.0f;
        #pragma unroll
        for (int s = 0; s < SS; s++) { ea += ex2a(Ma[s]-mxa); eb += ex2a(Mb[s]-mxb); }
        G1a = -((mxa - lbA) + lg2a(ea));
        G1b = -((mxb - lbB) + lg2a(eb));
        g2s[l] = G1a; g2s[l+32] = G1b;
    }
    __syncwarp();

    // ---------------- sweep-1 f + Wb build (row fs, k-half kh) ----------------
    const int fs = l & 15, kh = l >> 4;
    ull Wbq2[16];
    {
        float af[32];
        const float* Mrow = Msh + fs*MST + kh*32;
        const float* Gp   = g2s + kh*32;
        #pragma unroll
        for (int j = 0; j < 32; j++) af[j] = Gp[j] + Mrow[j];
        float mf = af[0];
        #pragma unroll
        for (int j = 1; j < 32; j++) mf = fmaxf(mf, af[j]);
        float ef = 0.0f;
        #pragma unroll
        for (int j = 0; j < 32; j++) ef += ex2a(af[j] - mf);
        float mo = __shfl_xor_sync(FULLM, mf, 16);
        float eo = __shfl_xor_sync(FULLM, ef, 16);
        float M2 = fmaxf(mf, mo);
        ef = ef*ex2a(mf - M2) + eo*ex2a(mo - M2);
        float F1 = -(M2 + lg2a(ef));                   // same in both halves
        #pragma unroll
        for (int j = 0; j < 16; j++)
            Wbq2[j] = pk2(ex2a(F1 + af[2*j]), ex2a(F1 + af[2*j+1]));
        if (l < 16) f2s[fs] = F1;
    }
    __syncwarp();

    // ---------------- W2 (g-direction, own columns) ----------------
    ull W2a[8], W2b[8];
    {
        const float glA = G1a - lbA, glB = G1b - lbB;
        #pragma unroll
        for (int j = 0; j < 8; j++) {
            float f0 = f2s[2*j], f1 = f2s[2*j+1];
            W2a[j] = pk2(ex2a(f0 + glA + Msh[(2*j)*MST + l]),
                         ex2a(f1 + glA + Msh[(2*j+1)*MST + l]));
            W2b[j] = pk2(ex2a(f0 + glB + Msh[(2*j)*MST + l + 32]),
                         ex2a(f1 + glB + Msh[(2*j+1)*MST + l + 32]));
        }
    }
    __syncwarp();                          // F1 reads done before u reset
    if (l < 16) f2s[l] = 1.0f;
    __syncwarp();

    // ---------------- linear sweeps (warp-synchronous, early exit) ------------
    float va = 1.0f, vb = 1.0f;
    const ull* const u2 = (const ull*)f2s;

    #pragma unroll 1
    for (int it = 1; it <= 20; it++) {
        // g: V per column
        ull A0 = 0ull, A1 = 0ull, B0 = 0ull, B1 = 0ull;
        #pragma unroll
        for (int j = 0; j < 8; j += 2) {
            ull u0 = u2[j], u1 = u2[j+1];
            ffma2(A0, u0, W2a[j]); ffma2(A1, u1, W2a[j+1]);
            ffma2(B0, u0, W2b[j]); ffma2(B1, u1, W2b[j+1]);
        }
        va = rcpa(fmaxf(unpack_add(A0) + unpack_add(A1), 1e-30f));
        vb = rcpa(fmaxf(unpack_add(B0) + unpack_add(B1), 1e-30f));
        g2s[l] = va; g2s[l+32] = vb;
        __syncwarp();
        // f: u per row (half-sums merged by shfl)
        const ull* Vp = (const ull*)(g2s + kh*32);
        ull R0 = 0ull, R1 = 0ull;
        #pragma unroll
        for (int j = 0; j < 16; j += 2) { ffma2(R0, Vp[j], Wbq2[j]); ffma2(R1, Vp[j+1], Wbq2[j+1]); }
        float rs = unpack_add(R0) + unpack_add(R1);
        rs += __shfl_xor_sync(FULLM, rs, 16);
        float uc = rcpa(fmaxf(rs, 1e-30f));
        bool ok = (fabsf(va - 1.0f) <= CTOL) && (fabsf(vb - 1.0f) <= CTOL)
               && (fabsf(uc - 1.0f) <= CTOL);
        if (l < 16) f2s[fs] = uc;
        __syncwarp();
        if (__all_sync(FULLM, ok)) break;

        // re-absorb (underflow ratchet; R10-validated schedule)
        if ((it & 3) == 0 && it != 20) {
            ull vva = pk2(va, va), vvb = pk2(vb, vb);
            #pragma unroll
            for (int j = 0; j < 8; j++) {
                ull uj = u2[j];
                W2a[j] = fmul2(W2a[j], fmul2(uj, vva));
                W2b[j] = fmul2(W2b[j], fmul2(uj, vvb));
            }
            float uf = f2s[fs];
            ull uu = pk2(uf, uf);
            const ull* Vq = (const ull*)(g2s + kh*32);
            #pragma unroll
            for (int j = 0; j < 16; j++) Wbq2[j] = fmul2(Wbq2[j], fmul2(uu, Vq[j]));
            __syncwarp();                  // absorb reads done before reset
            if (l < 16) f2s[l] = 1.0f;
            __syncwarp();
        }
    }

    // ---------------- histogram ----------------
    {
        ull A0 = 0ull, A1 = 0ull, B0 = 0ull, B1 = 0ull;
        #pragma unroll
        for (int j = 0; j < 8; j += 2) {
            ull u0 = u2[j], u1 = u2[j+1];
            ffma2(A0, u0, W2a[j]); ffma2(A1, u1, W2a[j+1]);
            ffma2(B0, u0, W2b[j]); ffma2(B1, u1, W2b[j+1]);
        }
        float ha = g_bk[l]    * va * (unpack_add(A0) + unpack_add(A1));
        float hb = g_bk[l+32] * vb * (unpack_add(B0) + unpack_add(B1));
        float t = ha + hb;
        #pragma unroll
        for (int o = 16; o; o >>= 1) t += __shfl_xor_sync(FULLM, t, o);
        float inv = rcpa(fmaxf(t, 1e-30f));

        int b = bidx[node];
        atomicAdd(&g_sums[b*KK + l],      ha * inv);
        atomicAdd(&g_sums[b*KK + l + 32], hb * inv);
        if (l == 0) atomicAdd(&g_counts[b], 1.0f);
    }
}

// ---------------------------------------------------------------------------
__global__ void final_kernel(float* __restrict__ out, int B)
{
    int b = blockIdx.x, k = threadIdx.x;
    if (b >= B) return;
    float c = g_counts[b];
    float v = (c > 0.0f) ? (g_sums[b*KK + k] / c) : g_bk[k];
    out[b*KK + k] = v;
}

// ---------------------------------------------------------------------------
extern "C" void kernel_launch(void* const* d_in, const int* in_sizes, int n_in,
                              void* d_out, int out_size)
{
    const float* x    = (const float*)d_in[0];   // [N,16,128] f32
    const int*   bi   = (const int*)  d_in[1];   // [N] int32
    const float* cb   = (const float*)d_in[2];   // [64,128] f32
    const float* lp   = (const float*)d_in[3];   // [64] f32
    int N = in_sizes[1];
    int B = out_size / KK;
    if (B > BMAX) B = BMAX;

    cudaFuncSetAttribute(node_kernel, cudaFuncAttributeMaxDynamicSharedMemorySize, DYN_BYTES);

    prep_kernel<<<64, 256>>>(cb, lp);
    node_kernel<<<(N + NPB - 1)/NPB, NTHR, DYN_BYTES>>>(x, bi, N);
    final_kernel<<<B, KK>>>((float*)d_out, B);
}

// round 17
// speedup vs baseline: 3.6258x; 1.4738x over previous
#include <cuda_runtime.h>
#include <cuda_bf16.h>
#include <cstdint>

// BarycentricPooling — warp-autonomous nodes, A-fragments direct from global.
//
// N=20000, S=16, D=128, K=64, B=256, eps=0.1, 21 sweeps (1 log + <=20 linear).
//
// mma.sync contracts position-wise: a consistent k-permutation of A and B
// fragments is exact. B stored in NATURAL k-order (smem, uint2 at 16ks+4tg
// gives b0=(k,k+1), b1=(k+2,k+3)); A fragment = ONE LDG.128 from global at the
// same k offset (a0=(v.x,v.y), a2=(v.z,v.w)), hi/lo bf16 split inline, ||x||^2
// accumulated in-lane. No A smem staging at all.
//
// Block = 256 threads = 8 warps = 8 nodes; only ONE bar.sync (B staging).
// Sinkhorn: R16-verbatim warp-synchronous code (sweep-1 log, absorbs at
// {4,8,12,16}, __all_sync early exit; 4.488e-4 validated), CTOL relaxed to
// 1e-4 (R4-vs-R10 evidence: exit fires only after numerics freeze).
//
// pad_kernel: 4th launch per call -> ncu (-s 5 -c 1) captures node_kernel.

#define SS    16
#define KK    64
#define DD    128
#define BMAX  256
#define NPB   8
#define NTHR  256
#define AST   144                 // B row stride in halves (72 words == 8 mod 32)
#define MST   66
#define NODEW 1152                // per-node smem floats: 16*66 + 64 + 16 (+pad)
#define L2E_EPS 14.4269504088896340736f
#define CTOL  1e-4f
#define FULLM 0xffffffffu

typedef unsigned long long ull;

__device__ __align__(16) __nv_bfloat16 g_Bt[2*KK*AST]; // [v][n][AST] natural k order
__device__ float g_y2[KK], g_lb2[KK], g_bk[KK];
__device__ float g_sums[BMAX*KK], g_counts[BMAX];

__device__ __forceinline__ float ex2a(float x){ float y; asm("ex2.approx.ftz.f32 %0, %1;" : "=f"(y) : "f"(x)); return y; }
__device__ __forceinline__ float lg2a(float x){ float y; asm("lg2.approx.ftz.f32 %0, %1;" : "=f"(y) : "f"(x)); return y; }
__device__ __forceinline__ float rcpa(float x){ float y; asm("rcp.approx.ftz.f32 %0, %1;" : "=f"(y) : "f"(x)); return y; }
__device__ __forceinline__ void ffma2(ull& d, ull a, ull b){
    asm("fma.rn.f32x2 %0, %1, %2, %0;" : "+l"(d) : "l"(a), "l"(b));
}
__device__ __forceinline__ ull fmul2(ull a, ull b){
    ull r; asm("mul.rn.f32x2 %0, %1, %2;" : "=l"(r) : "l"(a), "l"(b)); return r;
}
__device__ __forceinline__ float unpack_add(ull v){
    float lo = __uint_as_float((unsigned)(v & 0xffffffffull));
    float hi = __uint_as_float((unsigned)(v >> 32));
    return lo + hi;
}
__device__ __forceinline__ ull pk2(float lo, float hi){
    ull r; asm("mov.b64 %0, {%1,%2};" : "=l"(r) : "f"(lo), "f"(hi)); return r;
}
__device__ __forceinline__ uint32_t bfpack(float a, float b){
    __nv_bfloat162 t = __floats2bfloat162_rn(a, b);   // low half = a
    return *(uint32_t*)&t;
}
__device__ __forceinline__ void mma16816(float* c, uint32_t a0, uint32_t a1,
                                         uint32_t a2, uint32_t a3,
                                         uint32_t b0, uint32_t b1){
    asm volatile(
        "mma.sync.aligned.m16n8k16.row.col.f32.bf16.bf16.f32 "
        "{%0,%1,%2,%3}, {%4,%5,%6,%7}, {%8,%9}, {%0,%1,%2,%3};"
        : "+f"(c[0]), "+f"(c[1]), "+f"(c[2]), "+f"(c[3])
        : "r"(a0), "r"(a1), "r"(a2), "r"(a3), "r"(b0), "r"(b1));
}

// ---------------------------------------------------------------------------
__global__ void prep_kernel(const float* __restrict__ cb,
                            const float* __restrict__ lp)
{
    __shared__ float sm[2], se[2];
    int tid = threadIdx.x;
    int i = blockIdx.x * blockDim.x + tid;      // 0..16383

    if (i < BMAX*KK) g_sums[i] = 0.0f;
    if (i < BMAX)    g_counts[i] = 0.0f;

    if (i < KK*DD) {                      // split codebook hi/lo, NATURAL order
        int n = i >> 7, d = i & 127;
        float v = cb[n*DD + d];
        __nv_bfloat16 h = __float2bfloat16(v);
        float l = v - __bfloat162float(h);
        g_Bt[n*AST + d]          = h;
        g_Bt[KK*AST + n*AST + d] = __float2bfloat16(l);
    }
    if (blockIdx.x == 0) {
        if (tid < KK*4) {
            int k = tid >> 2, q = tid & 3;
            const float4* r = (const float4*)(cb + k*DD + q*32);
            float s = 0.0f;
            #pragma unroll
            for (int j = 0; j < 8; j++) { float4 v = r[j]; s += v.x*v.x + v.y*v.y + v.z*v.z + v.w*v.w; }
            s += __shfl_xor_sync(FULLM, s, 1);
            s += __shfl_xor_sync(FULLM, s, 2);
            if (q == 0) g_y2[k] = s;
        }
        float v = (tid < KK) ? lp[tid] : -1e30f;
        if (tid < KK) {
            float m = v;
            #pragma unroll
            for (int o = 16; o; o >>= 1) m = fmaxf(m, __shfl_xor_sync(FULLM, m, o));
            if ((tid & 31) == 0) sm[tid >> 5] = m;
        }
        __syncthreads();
        if (tid < KK) {
            float M = fmaxf(sm[0], sm[1]);
            float e = __expf(v - M);
            float s = e;
            #pragma unroll
            for (int o = 16; o; o >>= 1) s += __shfl_xor_sync(FULLM, s, o);
            if ((tid & 31) == 0) se[tid >> 5] = s;
        }
        __syncthreads();
        if (tid < KK) {
            float M = fmaxf(sm[0], sm[1]);
            float lb2 = (v - M) * 1.4426950408889634f - lg2a(se[0] + se[1]);
            g_lb2[tid] = lb2;
            g_bk[tid]  = ex2a(lb2);
        }
    }
}

// ---------------------------------------------------------------------------
// dyn smem: bS 2*64*AST halves (36864B) + 8 nodes x NODEW floats (4608B each)
#define DYN_BYTES (2*KK*AST*2 + NPB*NODEW*4)   // 73728

__global__ __launch_bounds__(NTHR, 2)
void node_kernel(const float* __restrict__ x,
                 const int*   __restrict__ bidx,
                 int n_nodes)
{
    extern __shared__ __align__(16) char dyn[];
    __nv_bfloat16* const bS = (__nv_bfloat16*)dyn;       // [v][64][AST]
    float* const nodeS = (float*)(dyn + 2*KK*AST*2);     // [NPB][NODEW]

    const int tid = threadIdx.x;
    const int w   = tid >> 5;             // warp = node 0..7
    const int l   = tid & 31;
    const int g8  = l >> 2;               // mma groupID
    const int tg  = l & 3;                // mma thread-in-group
    const int node = blockIdx.x * NPB + w;
    const bool valid = node < n_nodes;

    // ---------------- stage B (whole block) ----------------
    {
        const uint4* bg = (const uint4*)g_Bt;
        uint4* bs4 = (uint4*)bS;
        for (int i = tid; i < 2304; i += NTHR) bs4[i] = bg[i];
    }
    __syncthreads();                      // the ONLY block barrier

    if (!valid) return;

    // ---------------- GEMM: A direct from global, 4-pass split ----------------
    float c[8][4];
    #pragma unroll
    for (int nt = 0; nt < 8; nt++)
        #pragma unroll
        for (int j = 0; j < 4; j++) c[nt][j] = 0.0f;

    float x20 = 0.0f, x21 = 0.0f;         // ||x_row||^2 partials, rows g8/g8+8
    {
        const float* xg = x + (size_t)node*(SS*DD);
        const __nv_bfloat16* bHi = bS;
        const __nv_bfloat16* bLo = bS + KK*AST;
        #pragma unroll 2
        for (int ks = 0; ks < 8; ks++) {
            const int o = ks*16 + 4*tg;
            float4 v0 = *(const float4*)(xg + g8*DD     + o);
            float4 v1 = *(const float4*)(xg + (g8+8)*DD + o);
            x20 += v0.x*v0.x + v0.y*v0.y + v0.z*v0.z + v0.w*v0.w;
            x21 += v1.x*v1.x + v1.y*v1.y + v1.z*v1.z + v1.w*v1.w;
            // hi fragments (a0,a2) rows g8 / (a1,a3) row g8+8
            __nv_bfloat162 h0a = __floats2bfloat162_rn(v0.x, v0.y);
            __nv_bfloat162 h0b = __floats2bfloat162_rn(v0.z, v0.w);
            __nv_bfloat162 h1a = __floats2bfloat162_rn(v1.x, v1.y);
            __nv_bfloat162 h1b = __floats2bfloat162_rn(v1.z, v1.w);
            uint32_t Ah0 = *(uint32_t*)&h0a, Ah2 = *(uint32_t*)&h0b;
            uint32_t Ah1 = *(uint32_t*)&h1a, Ah3 = *(uint32_t*)&h1b;
            uint32_t Al0 = bfpack(v0.x - __bfloat162float(h0a.x), v0.y - __bfloat162float(h0a.y));
            uint32_t Al2 = bfpack(v0.z - __bfloat162float(h0b.x), v0.w - __bfloat162float(h0b.y));
            uint32_t Al1 = bfpack(v1.x - __bfloat162float(h1a.x), v1.y - __bfloat162float(h1a.y));
            uint32_t Al3 = bfpack(v1.z - __bfloat162float(h1b.x), v1.w - __bfloat162float(h1b.y));
            #pragma unroll
            for (int nt = 0; nt < 8; nt++) {
                uint2 Bh = *(const uint2*)(bHi + (nt*8+g8)*AST + o);
                uint2 Bl = *(const uint2*)(bLo + (nt*8+g8)*AST + o);
                mma16816(c[nt], Ah0, Ah1, Ah2, Ah3, Bh.x, Bh.y);  // hh
                mma16816(c[nt], Ah0, Ah1, Ah2, Ah3, Bl.x, Bl.y);  // hl
                mma16816(c[nt], Al0, Al1, Al2, Al3, Bh.x, Bh.y);  // lh
                mma16816(c[nt], Al0, Al1, Al2, Al3, Bl.x, Bl.y);  // ll
            }
        }
    }
    // full row sums: reduce over quad (lanes 4*g8+tg share rows g8/g8+8)
    x20 += __shfl_xor_sync(FULLM, x20, 1);
    x20 += __shfl_xor_sync(FULLM, x20, 2);
    x21 += __shfl_xor_sync(FULLM, x21, 1);
    x21 += __shfl_xor_sync(FULLM, x21, 2);

    // ---------------- C -> M = -C*log2e/eps + log2(b) ----------------
    float* const Msh = nodeS + w*NODEW;                // 16 x MST
    float* const g2s = Msh + SS*MST;                   // [64]
    float* const f2s = g2s + KK;                       // [16]
    {
        #pragma unroll
        for (int nt = 0; nt < 8; nt++) {
            int n0 = nt*8 + 2*tg;
            float y20 = g_y2[n0],  y21 = g_y2[n0+1];
            float lb0 = g_lb2[n0], lb1 = g_lb2[n0+1];
            float m00 = -fmaxf(x20 + y20 - 2.0f*c[nt][0], 0.0f)*L2E_EPS + lb0;
            float m01 = -fmaxf(x20 + y21 - 2.0f*c[nt][1], 0.0f)*L2E_EPS + lb1;
            float m10 = -fmaxf(x21 + y20 - 2.0f*c[nt][2], 0.0f)*L2E_EPS + lb0;
            float m11 = -fmaxf(x21 + y21 - 2.0f*c[nt][3], 0.0f)*L2E_EPS + lb1;
            *(float2*)(Msh + g8*MST     + n0) = make_float2(m00, m01);
            *(float2*)(Msh + (g8+8)*MST + n0) = make_float2(m10, m11);
        }
    }
    __syncwarp();

    // ---------------- sweep-1 g: G1 per column (cols l, l+32) ----------------
    const float lbA = g_lb2[l], lbB = g_lb2[l+32];
    float G1a, G1b;
    {
        float Ma[SS], Mb[SS];
        #pragma unroll
        for (int s = 0; s < SS; s++) { Ma[s] = Msh[s*MST + l]; Mb[s] = Msh[s*MST + l + 32]; }
        float mxa = Ma[0], mxb = Mb[0];
        #pragma unroll
        for (int s = 1; s < SS; s++) { mxa = fmaxf(mxa, Ma[s]); mxb = fmaxf(mxb, Mb[s]); }
        float ea = 0.0f, eb = 0.0f;
        #pragma unroll
        for (int s = 0; s < SS; s++) { ea += ex2a(Ma[s]-mxa); eb += ex2a(Mb[s]-mxb); }
        G1a = -((mxa - lbA) + lg2a(ea));
        G1b = -((mxb - lbB) + lg2a(eb));
        g2s[l] = G1a; g2s[l+32] = G1b;
    }
    __syncwarp();

    // ---------------- sweep-1 f + Wb build (row fs, k-half kh) ----------------
    const int fs = l & 15, kh = l >> 4;
    ull Wbq2[16];
    {
        float af[32];
        const float* Mrow = Msh + fs*MST + kh*32;
        const float* Gp   = g2s + kh*32;
        #pragma unroll
        for (int j = 0; j < 32; j++) af[j] = Gp[j] + Mrow[j];
        float mf = af[0];
        #pragma unroll
        for (int j = 1; j < 32; j++) mf = fmaxf(mf, af[j]);
        float ef = 0.0f;
        #pragma unroll
        for (int j = 0; j < 32; j++) ef += ex2a(af[j] - mf);
        float mo = __shfl_xor_sync(FULLM, mf, 16);
        float eo = __shfl_xor_sync(FULLM, ef, 16);
        float M2 = fmaxf(mf, mo);
        ef = ef*ex2a(mf - M2) + eo*ex2a(mo - M2);
        float F1 = -(M2 + lg2a(ef));                   // same in both halves
        #pragma unroll
        for (int j = 0; j < 16; j++)
            Wbq2[j] = pk2(ex2a(F1 + af[2*j]), ex2a(F1 + af[2*j+1]));
        if (l < 16) f2s[fs] = F1;
    }
    __syncwarp();

    // ---------------- W2 (g-direction, own columns) ----------------
    ull W2a[8], W2b[8];
    {
        const float glA = G1a - lbA, glB = G1b - lbB;
        #pragma unroll
        for (int j = 0; j < 8; j++) {
            float f0 = f2s[2*j], f1 = f2s[2*j+1];
            W2a[j] = pk2(ex2a(f0 + glA + Msh[(2*j)*MST + l]),
                         ex2a(f1 + glA + Msh[(2*j+1)*MST + l]));
            W2b[j] = pk2(ex2a(f0 + glB + Msh[(2*j)*MST + l + 32]),
                         ex2a(f1 + glB + Msh[(2*j+1)*MST + l + 32]));
        }
    }
    __syncwarp();                          // F1 reads done before u reset
    if (l < 16) f2s[l] = 1.0f;
    __syncwarp();

    // ---------------- linear sweeps (warp-synchronous, early exit) ------------
    float va = 1.0f, vb = 1.0f;
    const ull* const u2 = (const ull*)f2s;

    #pragma unroll 1
    for (int it = 1; it <= 20; it++) {
        // g: V per column
        ull A0 = 0ull, A1 = 0ull, B0 = 0ull, B1 = 0ull;
        #pragma unroll
        for (int j = 0; j < 8; j += 2) {
            ull u0 = u2[j], u1 = u2[j+1];
            ffma2(A0, u0, W2a[j]); ffma2(A1, u1, W2a[j+1]);
            ffma2(B0, u0, W2b[j]); ffma2(B1, u1, W2b[j+1]);
        }
        va = rcpa(fmaxf(unpack_add(A0) + unpack_add(A1), 1e-30f));
        vb = rcpa(fmaxf(unpack_add(B0) + unpack_add(B1), 1e-30f));
        g2s[l] = va; g2s[l+32] = vb;
        __syncwarp();
        // f: u per row (half-sums merged by shfl)
        const ull* Vp = (const ull*)(g2s + kh*32);
        ull R0 = 0ull, R1 = 0ull;
        #pragma unroll
        for (int j = 0; j < 16; j += 2) { ffma2(R0, Vp[j], Wbq2[j]); ffma2(R1, Vp[j+1], Wbq2[j+1]); }
        float rs = unpack_add(R0) + unpack_add(R1);
        rs += __shfl_xor_sync(FULLM, rs, 16);
        float uc = rcpa(fmaxf(rs, 1e-30f));
        bool ok = (fabsf(va - 1.0f) <= CTOL) && (fabsf(vb - 1.0f) <= CTOL)
               && (fabsf(uc - 1.0f) <= CTOL);
        if (l < 16) f2s[fs] = uc;
        __syncwarp();
        if (__all_sync(FULLM, ok)) break;

        // re-absorb (underflow ratchet; R10-validated schedule)
        if ((it & 3) == 0 && it != 20) {
            ull vva = pk2(va, va), vvb = pk2(vb, vb);
            #pragma unroll
            for (int j = 0; j < 8; j++) {
                ull uj = u2[j];
                W2a[j] = fmul2(W2a[j], fmul2(uj, vva));
                W2b[j] = fmul2(W2b[j], fmul2(uj, vvb));
            }
            float uf = f2s[fs];
            ull uu = pk2(uf, uf);
            const ull* Vq = (const ull*)(g2s + kh*32);
            #pragma unroll
            for (int j = 0; j < 16; j++) Wbq2[j] = fmul2(Wbq2[j], fmul2(uu, Vq[j]));
            __syncwarp();                  // absorb reads done before reset
            if (l < 16) f2s[l] = 1.0f;
            __syncwarp();
        }
    }

    // ---------------- histogram ----------------
    {
        ull A0 = 0ull, A1 = 0ull, B0 = 0ull, B1 = 0ull;
        #pragma unroll
        for (int j = 0; j < 8; j += 2) {
            ull u0 = u2[j], u1 = u2[j+1];
            ffma2(A0, u0, W2a[j]); ffma2(A1, u1, W2a[j+1]);
            ffma2(B0, u0, W2b[j]); ffma2(B1, u1, W2b[j+1]);
        }
        float ha = g_bk[l]    * va * (unpack_add(A0) + unpack_add(A1));
        float hb = g_bk[l+32] * vb * (unpack_add(B0) + unpack_add(B1));
        float t = ha + hb;
        #pragma unroll
        for (int o = 16; o; o >>= 1) t += __shfl_xor_sync(FULLM, t, o);
        float inv = rcpa(fmaxf(t, 1e-30f));

        int b = bidx[node];
        atomicAdd(&g_sums[b*KK + l],      ha * inv);
        atomicAdd(&g_sums[b*KK + l + 32], hb * inv);
        if (l == 0) atomicAdd(&g_counts[b], 1.0f);
    }
}

// ---------------------------------------------------------------------------
__global__ void final_kernel(float* __restrict__ out, int B)
{
    int b = blockIdx.x, k = threadIdx.x;
    if (b >= B) return;
    float c = g_counts[b];
    float v = (c > 0.0f) ? (g_sums[b*KK + k] / c) : g_bk[k];
    out[b*KK + k] = v;
}

// pad launch: shifts ncu's (-s 5 -c 1) capture window onto node_kernel
// (4 launches/call -> node_kernel at positions 2,6,10,...).
__global__ void pad_kernel() {}

// ---------------------------------------------------------------------------
extern "C" void kernel_launch(void* const* d_in, const int* in_sizes, int n_in,
                              void* d_out, int out_size)
{
    const float* x    = (const float*)d_in[0];   // [N,16,128] f32
    const int*   bi   = (const int*)  d_in[1];   // [N] int32
    const float* cb   = (const float*)d_in[2];   // [64,128] f32
    const float* lp   = (const float*)d_in[3];   // [64] f32
    int N = in_sizes[1];
    int B = out_size / KK;
    if (B > BMAX) B = BMAX;

    cudaFuncSetAttribute(node_kernel, cudaFuncAttributeMaxDynamicSharedMemorySize, DYN_BYTES);

    prep_kernel<<<64, 256>>>(cb, lp);
    node_kernel<<<(N + NPB - 1)/NPB, NTHR, DYN_BYTES>>>(x, bi, N);
    final_kernel<<<B, KK>>>((float*)d_out, B);
    pad_kernel<<<1, 1>>>();
}